// round 1
// baseline (speedup 1.0000x reference)
#include <cuda_runtime.h>

#define B_SZ   16
#define N_SZ   128
#define ROWS   2048        // B*N
#define K_NB   16
#define D_SZ   512
#define C_SZ   2048        // 4*D
#define ALPHA  0.2f
#define BN_EPS 1e-5f
#define L2_EPS 1e-12f

// ---------------- device scratch (no allocations allowed) ----------------
__device__ float g_a_self[ROWS];
__device__ float g_a_nei[ROWS];
__device__ float g_y[ROWS * D_SZ];          // x @ Wn^T + Wn_b   (4 MB)
__device__ float g_h[ROWS * C_SZ];          // concat rows       (16 MB)
__device__ float g_sum[C_SZ];
__device__ float g_sumsq[C_SZ];

// ---------------- kernel 1: attention dot products + zero stats ----------
// grid 256 x 256 threads. one warp per row (8 rows/block).
__global__ void k_prep(const float* __restrict__ x, const float* __restrict__ Wa) {
    int tid = threadIdx.x;
    int gid = blockIdx.x * 256 + tid;
    if (gid < C_SZ) { g_sum[gid] = 0.f; g_sumsq[gid] = 0.f; }

    int wid = tid >> 5, lane = tid & 31;
    int row = blockIdx.x * 8 + wid;
    const float* xr = x + (size_t)row * D_SZ;
    float s1 = 0.f, s2 = 0.f;
    #pragma unroll 4
    for (int i = lane; i < D_SZ; i += 32) {
        float v = xr[i];
        s1 += v * Wa[i];
        s2 += v * Wa[D_SZ + i];
    }
    #pragma unroll
    for (int o = 16; o > 0; o >>= 1) {
        s1 += __shfl_down_sync(0xffffffffu, s1, o);
        s2 += __shfl_down_sync(0xffffffffu, s2, o);
    }
    if (lane == 0) { g_a_self[row] = s1; g_a_nei[row] = s2; }
}

// ---------------- kernel 2: two GEMMs (2048x512x512 each) ----------------
// z=0: g_h[:,0:512] = X @ Wx^T + Wx_b   (ldc = 2048)
// z=1: g_y          = X @ Wn^T + Wn_b   (ldc = 512)
// 64x64 tile, BK=16, 256 threads, 4x4 per thread.
__global__ void k_gemm(const float* __restrict__ X,
                       const float* __restrict__ Wx, const float* __restrict__ Wxb,
                       const float* __restrict__ Wn, const float* __restrict__ Wnb) {
    const float* W  = blockIdx.z ? Wn  : Wx;
    const float* bi = blockIdx.z ? Wnb : Wxb;
    float* C        = blockIdx.z ? g_y : g_h;
    int ldc         = blockIdx.z ? D_SZ : C_SZ;

    __shared__ float As[16][64];
    __shared__ float Bs[16][64];

    int tid = threadIdx.x;
    int bm = blockIdx.y * 64;
    int bn = blockIdx.x * 64;

    int lm = tid >> 2;            // 0..63
    int lk = (tid & 3) * 4;       // 0,4,8,12
    int tn = (tid & 15) * 4;      // 0..60
    int tm = (tid >> 4) * 4;      // 0..60

    float acc[4][4] = {};

    for (int k0 = 0; k0 < D_SZ; k0 += 16) {
        float4 a = *(const float4*)&X[(size_t)(bm + lm) * D_SZ + k0 + lk];
        float4 b = *(const float4*)&W[(size_t)(bn + lm) * D_SZ + k0 + lk];
        As[lk + 0][lm] = a.x; As[lk + 1][lm] = a.y;
        As[lk + 2][lm] = a.z; As[lk + 3][lm] = a.w;
        Bs[lk + 0][lm] = b.x; Bs[lk + 1][lm] = b.y;
        Bs[lk + 2][lm] = b.z; Bs[lk + 3][lm] = b.w;
        __syncthreads();

        #pragma unroll
        for (int k = 0; k < 16; k++) {
            float4 av = *(const float4*)&As[k][tm];
            float4 bv = *(const float4*)&Bs[k][tn];
            acc[0][0] += av.x * bv.x; acc[0][1] += av.x * bv.y;
            acc[0][2] += av.x * bv.z; acc[0][3] += av.x * bv.w;
            acc[1][0] += av.y * bv.x; acc[1][1] += av.y * bv.y;
            acc[1][2] += av.y * bv.z; acc[1][3] += av.y * bv.w;
            acc[2][0] += av.z * bv.x; acc[2][1] += av.z * bv.y;
            acc[2][2] += av.z * bv.z; acc[2][3] += av.z * bv.w;
            acc[3][0] += av.w * bv.x; acc[3][1] += av.w * bv.y;
            acc[3][2] += av.w * bv.z; acc[3][3] += av.w * bv.w;
        }
        __syncthreads();
    }

    float4 bi4 = *(const float4*)&bi[bn + tn];
    #pragma unroll
    for (int i = 0; i < 4; i++) {
        float4 o;
        o.x = acc[i][0] + bi4.x;
        o.y = acc[i][1] + bi4.y;
        o.z = acc[i][2] + bi4.z;
        o.w = acc[i][3] + bi4.w;
        *(float4*)&C[(size_t)(bm + tm + i) * ldc + bn + tn] = o;
    }
}

// ---------------- kernel 3: softmax + gather-aggregate + L2norm + relu ----
// one block (256 threads) per row bn.
__global__ void k_row(const int* __restrict__ i1, const int* __restrict__ i2,
                      const int* __restrict__ i3) {
    int row = blockIdx.x;
    int b = row >> 7;          // row / 128
    int n = row & 127;

    __shared__ float sh[C_SZ];          // full concat row, 8 KB
    __shared__ float w_s[3][16];
    __shared__ int   ni_s[3][16];
    __shared__ float red[9];

    int tid = threadIdx.x;

    // edge scores (48 of them)
    if (tid < 48) {
        int br = tid >> 4, k = tid & 15;
        const int* ip = (br == 0) ? i1 : (br == 1) ? i2 : i3;
        int m = ip[n * K_NB + k];
        float e = g_a_self[row] + g_a_nei[b * N_SZ + m];
        e = (e > 0.f) ? e : ALPHA * e;
        w_s[br][k] = e;
        ni_s[br][k] = b * N_SZ + m;
    }
    __syncthreads();

    // softmax over K=16, one thread per branch
    if (tid < 3) {
        float mx = -1e30f;
        #pragma unroll
        for (int k = 0; k < 16; k++) mx = fmaxf(mx, w_s[tid][k]);
        float s = 0.f;
        #pragma unroll
        for (int k = 0; k < 16; k++) {
            float ev = __expf(w_s[tid][k] - mx);
            w_s[tid][k] = ev; s += ev;
        }
        float inv = 1.f / s;
        #pragma unroll
        for (int k = 0; k < 16; k++) w_s[tid][k] *= inv;
    }
    __syncthreads();

    // self branch (already computed by GEMM into g_h cols [0,512))
    sh[tid]       = g_h[(size_t)row * C_SZ + tid];
    sh[tid + 256] = g_h[(size_t)row * C_SZ + tid + 256];

    // neighbor branches: weighted gather over y (L2 resident)
    #pragma unroll
    for (int br = 0; br < 3; br++) {
        #pragma unroll
        for (int rep = 0; rep < 2; rep++) {
            int d = tid + rep * 256;
            float acc = 0.f;
            #pragma unroll
            for (int k = 0; k < 16; k++)
                acc += w_s[br][k] * g_y[(size_t)ni_s[br][k] * D_SZ + d];
            sh[(br + 1) * D_SZ + d] = acc;
        }
    }
    __syncthreads();

    // row sum of squares -> L2 norm
    float ss = 0.f;
    #pragma unroll
    for (int j = 0; j < 8; j++) {
        float v = sh[tid + j * 256];
        ss += v * v;
    }
    #pragma unroll
    for (int o = 16; o > 0; o >>= 1) ss += __shfl_down_sync(0xffffffffu, ss, o);
    if ((tid & 31) == 0) red[tid >> 5] = ss;
    __syncthreads();
    if (tid == 0) {
        float t = 0.f;
        #pragma unroll
        for (int i = 0; i < 8; i++) t += red[i];
        red[8] = 1.f / fmaxf(sqrtf(t), L2_EPS);
    }
    __syncthreads();
    float inv = red[8];

    #pragma unroll
    for (int j = 0; j < 8; j++) {
        int c = tid + j * 256;
        float v = sh[c] * inv;
        g_h[(size_t)row * C_SZ + c] = (v > 0.f) ? v : 0.f;
    }
}

// ---------------- kernel 4: channel sum / sumsq ---------------------------
// grid (8, 16): x -> channel group of 256, y -> row chunk of 128.
__global__ void k_stats() {
    int c  = blockIdx.x * 256 + threadIdx.x;
    int r0 = blockIdx.y * 128;
    float s = 0.f, q = 0.f;
    for (int r = r0; r < r0 + 128; r++) {
        float v = g_h[(size_t)r * C_SZ + c];
        s += v; q += v * v;
    }
    atomicAdd(&g_sum[c], s);
    atomicAdd(&g_sumsq[c], q);
}

// ---------------- kernel 5: batchnorm affine -> output --------------------
__global__ void k_final(const float* __restrict__ gamma, const float* __restrict__ beta,
                        float* __restrict__ out) {
    int gid = blockIdx.x * 256 + threadIdx.x;
    int e = gid * 4;
    int c = e & (C_SZ - 1);

    float4 h  = *(const float4*)&g_h[e];
    float4 sm = *(const float4*)&g_sum[c];
    float4 sq = *(const float4*)&g_sumsq[c];
    float4 ga = *(const float4*)&gamma[c];
    float4 be = *(const float4*)&beta[c];

    const float invn = 1.f / (float)ROWS;
    float4 o;
    {
        float mu = sm.x * invn; float var = sq.x * invn - mu * mu;
        o.x = (h.x - mu) * rsqrtf(var + BN_EPS) * ga.x + be.x;
    }
    {
        float mu = sm.y * invn; float var = sq.y * invn - mu * mu;
        o.y = (h.y - mu) * rsqrtf(var + BN_EPS) * ga.y + be.y;
    }
    {
        float mu = sm.z * invn; float var = sq.z * invn - mu * mu;
        o.z = (h.z - mu) * rsqrtf(var + BN_EPS) * ga.z + be.z;
    }
    {
        float mu = sm.w * invn; float var = sq.w * invn - mu * mu;
        o.w = (h.w - mu) * rsqrtf(var + BN_EPS) * ga.w + be.w;
    }
    *(float4*)&out[e] = o;
}

// ---------------- launch ---------------------------------------------------
extern "C" void kernel_launch(void* const* d_in, const int* in_sizes, int n_in,
                              void* d_out, int out_size) {
    const float* x     = (const float*)d_in[0];
    const int*   i1    = (const int*)  d_in[1];
    const int*   i2    = (const int*)  d_in[2];
    const int*   i3    = (const int*)  d_in[3];
    const float* Wxw   = (const float*)d_in[4];
    const float* Wxb   = (const float*)d_in[5];
    const float* Wnw   = (const float*)d_in[6];
    const float* Wnb   = (const float*)d_in[7];
    const float* Wa    = (const float*)d_in[8];
    const float* gamma = (const float*)d_in[9];
    const float* beta  = (const float*)d_in[10];
    float* out = (float*)d_out;

    k_prep<<<256, 256>>>(x, Wa);
    k_gemm<<<dim3(8, 32, 2), 256>>>(x, Wxw, Wxb, Wnw, Wnb);
    k_row<<<ROWS, 256>>>(i1, i2, i3);
    k_stats<<<dim3(8, 16), 256>>>();
    k_final<<<(ROWS * C_SZ) / (256 * 4), 256>>>(gamma, beta, out);
}

// round 2
// speedup vs baseline: 1.5684x; 1.5684x over previous
#include <cuda_runtime.h>
#include <cuda_bf16.h>
#include <cstdint>

#define B_SZ   16
#define N_SZ   128
#define ROWS   2048        // B*N
#define K_NB   16
#define D_SZ   512
#define C_SZ   2048        // 4*D
#define ALPHA  0.2f
#define BN_EPS 1e-5f
#define L2_EPS 1e-12f

// ---------------- device scratch (no allocations allowed) ----------------
__device__ float g_a_self[ROWS];
__device__ float g_a_nei[ROWS];
__device__ float g_y[ROWS * D_SZ];          // x @ Wn^T + Wn_b   (4 MB)
__device__ float g_h[ROWS * C_SZ];          // concat rows       (16 MB)
__device__ float g_sum[C_SZ];
__device__ float g_sumsq[C_SZ];

__device__ __nv_bfloat16 g_xhi[ROWS * D_SZ];
__device__ __nv_bfloat16 g_xlo[ROWS * D_SZ];
__device__ __nv_bfloat16 g_wxhi[D_SZ * D_SZ];
__device__ __nv_bfloat16 g_wxlo[D_SZ * D_SZ];
__device__ __nv_bfloat16 g_wnhi[D_SZ * D_SZ];
__device__ __nv_bfloat16 g_wnlo[D_SZ * D_SZ];

// ---------------- kernel 1: attention dot products + zero stats ----------
__global__ void k_prep(const float* __restrict__ x, const float* __restrict__ Wa) {
    int tid = threadIdx.x;
    int gid = blockIdx.x * 256 + tid;
    if (gid < C_SZ) { g_sum[gid] = 0.f; g_sumsq[gid] = 0.f; }

    int wid = tid >> 5, lane = tid & 31;
    int row = blockIdx.x * 8 + wid;
    const float* xr = x + (size_t)row * D_SZ;
    float s1 = 0.f, s2 = 0.f;
    #pragma unroll 4
    for (int i = lane; i < D_SZ; i += 32) {
        float v = xr[i];
        s1 += v * Wa[i];
        s2 += v * Wa[D_SZ + i];
    }
    #pragma unroll
    for (int o = 16; o > 0; o >>= 1) {
        s1 += __shfl_down_sync(0xffffffffu, s1, o);
        s2 += __shfl_down_sync(0xffffffffu, s2, o);
    }
    if (lane == 0) { g_a_self[row] = s1; g_a_nei[row] = s2; }
}

// ---------------- kernel 2: fp32 -> bf16 hi/lo split ----------------------
__device__ __forceinline__ void split1(float v, __nv_bfloat16& h, __nv_bfloat16& l) {
    h = __float2bfloat16_rn(v);
    l = __float2bfloat16_rn(v - __bfloat162float(h));
}

__device__ __forceinline__ void split4_store(float4 v, __nv_bfloat16* hi, __nv_bfloat16* lo, int idx4) {
    __nv_bfloat16 h0, h1, h2, h3, l0, l1, l2, l3;
    split1(v.x, h0, l0); split1(v.y, h1, l1);
    split1(v.z, h2, l2); split1(v.w, h3, l3);
    __nv_bfloat162 ph0(h0, h1), ph1(h2, h3), pl0(l0, l1), pl1(l2, l3);
    uint2 uh, ul;
    uh.x = *(uint32_t*)&ph0; uh.y = *(uint32_t*)&ph1;
    ul.x = *(uint32_t*)&pl0; ul.y = *(uint32_t*)&pl1;
    *(uint2*)&hi[idx4 * 4] = uh;
    *(uint2*)&lo[idx4 * 4] = ul;
}

// grid 1024 x 256 = 262144 threads
__global__ void k_conv(const float* __restrict__ x, const float* __restrict__ Wx,
                       const float* __restrict__ Wn) {
    int t = blockIdx.x * 256 + threadIdx.x;
    // x: 1,048,576 elems = 262,144 float4
    split4_store(((const float4*)x)[t], g_xhi, g_xlo, t);
    if (t < 65536) {
        split4_store(((const float4*)Wx)[t], g_wxhi, g_wxlo, t);
    } else if (t < 131072) {
        int u = t - 65536;
        split4_store(((const float4*)Wn)[u], g_wnhi, g_wnlo, u);
    }
}

// ---------------- kernel 3: tensor-core GEMMs -----------------------------
// C[m][n] = sum_k A[m,k]*W[n,k] with A = x_hi + x_lo, W = W_hi + W_lo
// computed as 3 bf16 passes: (hi,hi), (hi,lo), (lo,hi), fp32 accum.
// Block tile 128x128, 8 warps (2m x 4n), warp tile 64x32, BK=32.
#define SSTRIDE 40   // smem row stride in bf16 units (conflict-free, 16B aligned)

#define MMA16816(d, a, b0v, b1v) \
    asm volatile("mma.sync.aligned.m16n8k16.row.col.f32.bf16.bf16.f32 " \
        "{%0,%1,%2,%3}, {%4,%5,%6,%7}, {%8,%9}, {%0,%1,%2,%3};" \
        : "+f"(d[0]), "+f"(d[1]), "+f"(d[2]), "+f"(d[3]) \
        : "r"(a[0]), "r"(a[1]), "r"(a[2]), "r"(a[3]), "r"(b0v), "r"(b1v))

__global__ __launch_bounds__(256) void k_tc(const float* __restrict__ Wxb,
                                            const float* __restrict__ Wnb) {
    __shared__ __nv_bfloat16 As[128 * SSTRIDE];
    __shared__ __nv_bfloat16 Bs[128 * SSTRIDE];

    int z = blockIdx.z;
    const __nv_bfloat16* Ap[3];
    const __nv_bfloat16* Bp[3];
    Ap[0] = g_xhi; Ap[1] = g_xhi; Ap[2] = g_xlo;
    const float* bias;
    float* C;
    int ldc;
    if (z == 0) { Bp[0] = g_wxhi; Bp[1] = g_wxlo; Bp[2] = g_wxhi; bias = Wxb; C = g_h; ldc = C_SZ; }
    else        { Bp[0] = g_wnhi; Bp[1] = g_wnlo; Bp[2] = g_wnhi; bias = Wnb; C = g_y; ldc = D_SZ; }

    int tid = threadIdx.x;
    int lane = tid & 31;
    int wid = tid >> 5;
    int wm = (wid >> 2) * 64;      // warp m offset in tile
    int wn = (wid & 3) * 32;       // warp n offset in tile
    int bm = blockIdx.y * 128;
    int bn = blockIdx.x * 128;

    // global load indexing: 2 uint4 per thread per tile
    int l0r = tid >> 2;
    int l0c = (tid & 3) * 8;
    int l1r = (tid + 256) >> 2;
    int l1c = l0c;

    float acc[4][4][4];
    #pragma unroll
    for (int i = 0; i < 4; i++)
        #pragma unroll
        for (int j = 0; j < 4; j++)
            #pragma unroll
            for (int q = 0; q < 4; q++) acc[i][j][q] = 0.f;

    #pragma unroll
    for (int p = 0; p < 3; p++) {
        const __nv_bfloat16* Agl = Ap[p];
        const __nv_bfloat16* Bgl = Bp[p];

        uint4 av0 = *(const uint4*)&Agl[(size_t)(bm + l0r) * D_SZ + l0c];
        uint4 av1 = *(const uint4*)&Agl[(size_t)(bm + l1r) * D_SZ + l1c];
        uint4 bv0 = *(const uint4*)&Bgl[(size_t)(bn + l0r) * D_SZ + l0c];
        uint4 bv1 = *(const uint4*)&Bgl[(size_t)(bn + l1r) * D_SZ + l1c];

        for (int k0 = 0; k0 < D_SZ; k0 += 32) {
            __syncthreads();
            *(uint4*)&As[l0r * SSTRIDE + l0c] = av0;
            *(uint4*)&As[l1r * SSTRIDE + l1c] = av1;
            *(uint4*)&Bs[l0r * SSTRIDE + l0c] = bv0;
            *(uint4*)&Bs[l1r * SSTRIDE + l1c] = bv1;
            __syncthreads();

            if (k0 + 32 < D_SZ) {
                int kn = k0 + 32;
                av0 = *(const uint4*)&Agl[(size_t)(bm + l0r) * D_SZ + kn + l0c];
                av1 = *(const uint4*)&Agl[(size_t)(bm + l1r) * D_SZ + kn + l1c];
                bv0 = *(const uint4*)&Bgl[(size_t)(bn + l0r) * D_SZ + kn + l0c];
                bv1 = *(const uint4*)&Bgl[(size_t)(bn + l1r) * D_SZ + kn + l1c];
            }

            #pragma unroll
            for (int ks = 0; ks < 2; ks++) {
                int c = ks * 16 + (lane & 3) * 2;
                uint32_t af[4][4];
                #pragma unroll
                for (int mf = 0; mf < 4; mf++) {
                    int r0 = wm + mf * 16 + (lane >> 2);
                    af[mf][0] = *(const uint32_t*)&As[r0 * SSTRIDE + c];
                    af[mf][1] = *(const uint32_t*)&As[(r0 + 8) * SSTRIDE + c];
                    af[mf][2] = *(const uint32_t*)&As[r0 * SSTRIDE + c + 8];
                    af[mf][3] = *(const uint32_t*)&As[(r0 + 8) * SSTRIDE + c + 8];
                }
                #pragma unroll
                for (int nf = 0; nf < 4; nf++) {
                    int n0 = wn + nf * 8 + (lane >> 2);
                    uint32_t b0 = *(const uint32_t*)&Bs[n0 * SSTRIDE + c];
                    uint32_t b1 = *(const uint32_t*)&Bs[n0 * SSTRIDE + c + 8];
                    #pragma unroll
                    for (int mf = 0; mf < 4; mf++)
                        MMA16816(acc[mf][nf], af[mf], b0, b1);
                }
            }
        }
    }

    // epilogue: add bias, store
    #pragma unroll
    for (int nf = 0; nf < 4; nf++) {
        int cidx = bn + wn + nf * 8 + (lane & 3) * 2;
        float2 bi = *(const float2*)&bias[cidx];
        #pragma unroll
        for (int mf = 0; mf < 4; mf++) {
            int r = bm + wm + mf * 16 + (lane >> 2);
            float2 v0, v1;
            v0.x = acc[mf][nf][0] + bi.x; v0.y = acc[mf][nf][1] + bi.y;
            v1.x = acc[mf][nf][2] + bi.x; v1.y = acc[mf][nf][3] + bi.y;
            *(float2*)&C[(size_t)r * ldc + cidx] = v0;
            *(float2*)&C[(size_t)(r + 8) * ldc + cidx] = v1;
        }
    }
}

// ---------------- kernel 4: softmax + gather-aggregate + L2norm + relu ----
// one block (256 threads) per row.
__global__ void k_row(const int* __restrict__ i1, const int* __restrict__ i2,
                      const int* __restrict__ i3) {
    int row = blockIdx.x;
    int b = row >> 7;
    int n = row & 127;

    __shared__ float4 sh[512];          // full concat row (2048 floats)
    __shared__ float w_s[3][16];
    __shared__ int   ni_s[3][16];
    __shared__ float red[9];

    int tid = threadIdx.x;

    if (tid < 48) {
        int br = tid >> 4, k = tid & 15;
        const int* ip = (br == 0) ? i1 : (br == 1) ? i2 : i3;
        int m = ip[n * K_NB + k];
        float e = g_a_self[row] + g_a_nei[b * N_SZ + m];
        e = (e > 0.f) ? e : ALPHA * e;
        w_s[br][k] = e;
        ni_s[br][k] = b * N_SZ + m;
    }
    __syncthreads();

    if (tid < 3) {
        float mx = -1e30f;
        #pragma unroll
        for (int k = 0; k < 16; k++) mx = fmaxf(mx, w_s[tid][k]);
        float s = 0.f;
        #pragma unroll
        for (int k = 0; k < 16; k++) {
            float ev = __expf(w_s[tid][k] - mx);
            w_s[tid][k] = ev; s += ev;
        }
        float inv = 1.f / s;
        #pragma unroll
        for (int k = 0; k < 16; k++) w_s[tid][k] *= inv;
    }
    __syncthreads();

    const float4* h4 = (const float4*)&g_h[(size_t)row * C_SZ];
    const float4* y4 = (const float4*)g_y;

    #pragma unroll
    for (int rep = 0; rep < 2; rep++) {
        int item = tid + rep * 256;
        if (item < 128) {
            sh[item] = h4[item];
        } else {
            int br = (item - 128) >> 7;
            int f = item & 127;
            float4 a = make_float4(0.f, 0.f, 0.f, 0.f);
            #pragma unroll
            for (int k = 0; k < 16; k++) {
                float w = w_s[br][k];
                float4 v = y4[(size_t)ni_s[br][k] * 128 + f];
                a.x += w * v.x; a.y += w * v.y;
                a.z += w * v.z; a.w += w * v.w;
            }
            sh[item] = a;
        }
    }
    __syncthreads();

    float ss = 0.f;
    #pragma unroll
    for (int rep = 0; rep < 2; rep++) {
        float4 v = sh[tid + rep * 256];
        ss += v.x * v.x + v.y * v.y + v.z * v.z + v.w * v.w;
    }
    #pragma unroll
    for (int o = 16; o > 0; o >>= 1) ss += __shfl_down_sync(0xffffffffu, ss, o);
    if ((tid & 31) == 0) red[tid >> 5] = ss;
    __syncthreads();
    if (tid == 0) {
        float t = 0.f;
        #pragma unroll
        for (int i = 0; i < 8; i++) t += red[i];
        red[8] = 1.f / fmaxf(sqrtf(t), L2_EPS);
    }
    __syncthreads();
    float inv = red[8];

    float4* out4 = (float4*)&g_h[(size_t)row * C_SZ];
    #pragma unroll
    for (int rep = 0; rep < 2; rep++) {
        int item = tid + rep * 256;
        float4 v = sh[item];
        v.x = fmaxf(v.x * inv, 0.f); v.y = fmaxf(v.y * inv, 0.f);
        v.z = fmaxf(v.z * inv, 0.f); v.w = fmaxf(v.w * inv, 0.f);
        out4[item] = v;
    }
}

// ---------------- kernel 5: channel sum / sumsq ---------------------------
// grid (2, 64): x -> 256 float4-channels, y -> 32-row chunk.
__global__ void k_stats() {
    int c4 = blockIdx.x * 256 + threadIdx.x;     // 0..511
    int r0 = blockIdx.y * 32;
    const float4* h4 = (const float4*)g_h;
    float4 s = make_float4(0.f, 0.f, 0.f, 0.f);
    float4 q = make_float4(0.f, 0.f, 0.f, 0.f);
    #pragma unroll 4
    for (int r = r0; r < r0 + 32; r++) {
        float4 v = h4[(size_t)r * 512 + c4];
        s.x += v.x; s.y += v.y; s.z += v.z; s.w += v.w;
        q.x += v.x * v.x; q.y += v.y * v.y; q.z += v.z * v.z; q.w += v.w * v.w;
    }
    int c = c4 * 4;
    atomicAdd(&g_sum[c + 0], s.x); atomicAdd(&g_sum[c + 1], s.y);
    atomicAdd(&g_sum[c + 2], s.z); atomicAdd(&g_sum[c + 3], s.w);
    atomicAdd(&g_sumsq[c + 0], q.x); atomicAdd(&g_sumsq[c + 1], q.y);
    atomicAdd(&g_sumsq[c + 2], q.z); atomicAdd(&g_sumsq[c + 3], q.w);
}

// ---------------- kernel 6: batchnorm affine -> output --------------------
__global__ void k_final(const float* __restrict__ gamma, const float* __restrict__ beta,
                        float* __restrict__ out) {
    int gid = blockIdx.x * 256 + threadIdx.x;
    int e = gid * 4;
    int c = e & (C_SZ - 1);

    float4 h  = *(const float4*)&g_h[e];
    float4 sm = *(const float4*)&g_sum[c];
    float4 sq = *(const float4*)&g_sumsq[c];
    float4 ga = *(const float4*)&gamma[c];
    float4 be = *(const float4*)&beta[c];

    const float invn = 1.f / (float)ROWS;
    float4 o;
    { float mu = sm.x * invn; float var = sq.x * invn - mu * mu;
      o.x = (h.x - mu) * rsqrtf(var + BN_EPS) * ga.x + be.x; }
    { float mu = sm.y * invn; float var = sq.y * invn - mu * mu;
      o.y = (h.y - mu) * rsqrtf(var + BN_EPS) * ga.y + be.y; }
    { float mu = sm.z * invn; float var = sq.z * invn - mu * mu;
      o.z = (h.z - mu) * rsqrtf(var + BN_EPS) * ga.z + be.z; }
    { float mu = sm.w * invn; float var = sq.w * invn - mu * mu;
      o.w = (h.w - mu) * rsqrtf(var + BN_EPS) * ga.w + be.w; }
    *(float4*)&out[e] = o;
}

// ---------------- launch ---------------------------------------------------
extern "C" void kernel_launch(void* const* d_in, const int* in_sizes, int n_in,
                              void* d_out, int out_size) {
    const float* x     = (const float*)d_in[0];
    const int*   i1    = (const int*)  d_in[1];
    const int*   i2    = (const int*)  d_in[2];
    const int*   i3    = (const int*)  d_in[3];
    const float* Wxw   = (const float*)d_in[4];
    const float* Wxb   = (const float*)d_in[5];
    const float* Wnw   = (const float*)d_in[6];
    const float* Wnb   = (const float*)d_in[7];
    const float* Wa    = (const float*)d_in[8];
    const float* gamma = (const float*)d_in[9];
    const float* beta  = (const float*)d_in[10];
    float* out = (float*)d_out;

    k_prep<<<256, 256>>>(x, Wa);
    k_conv<<<1024, 256>>>(x, Wxw, Wnw);
    k_tc<<<dim3(4, 16, 2), 256>>>(Wxb, Wnb);
    k_row<<<ROWS, 256>>>(i1, i2, i3);
    k_stats<<<dim3(2, 64), 256>>>();
    k_final<<<(ROWS * C_SZ) / (256 * 4), 256>>>(gamma, beta, out);
}